// round 15
// baseline (speedup 1.0000x reference)
#include <cuda_runtime.h>
#include <cuda_fp16.h>
#include <math.h>
#include <stdint.h>

#define BB 2
#define TT 2048
#define CC 1024
#define HH 16
#define DD 64

// ---------------- device scratch (allocation-free rule) ----------------
__device__ __half g_xh[4194304],  g_xl[4194304];    // x split        [4096][1024]
__device__ __half g_wah[3145728], g_wal[3145728];   // W_attn split   [3072][1024]
__device__ __half g_wph[1048576], g_wpl[1048576];   // W_proj split   [1024][1024]
__device__ __half g_qh[4194304],  g_ql[4194304];    // q split  [B,H,T,D]
__device__ __half g_kh[4194304],  g_kl[4194304];
__device__ __half g_vh[4194304];                    // v hi only
__device__ __half g_yh[4194304];                    // attn out hi only [4096][1024]

// ---------------- helpers ----------------
__device__ __forceinline__ uint32_t smem_u32(const void* p) {
    uint32_t a;
    asm("{ .reg .u64 t; cvta.to.shared.u64 t, %1; cvt.u32.u64 %0, t; }" : "=r"(a) : "l"(p));
    return a;
}

__device__ __forceinline__ void mma_f16(float* c, const uint32_t* a, uint32_t b0, uint32_t b1) {
    asm volatile(
        "mma.sync.aligned.m16n8k16.row.col.f32.f16.f16.f32 "
        "{%0,%1,%2,%3}, {%4,%5,%6,%7}, {%8,%9}, {%0,%1,%2,%3};\n"
        : "+f"(c[0]), "+f"(c[1]), "+f"(c[2]), "+f"(c[3])
        : "r"(a[0]), "r"(a[1]), "r"(a[2]), "r"(a[3]), "r"(b0), "r"(b1));
}
__device__ __forceinline__ void ldsm4(uint32_t* r, uint32_t addr) {
    asm volatile("ldmatrix.sync.aligned.m8n8.x4.shared.b16 {%0,%1,%2,%3}, [%4];"
                 : "=r"(r[0]), "=r"(r[1]), "=r"(r[2]), "=r"(r[3]) : "r"(addr));
}
__device__ __forceinline__ void ldsm4t(uint32_t* r, uint32_t addr) {
    asm volatile("ldmatrix.sync.aligned.m8n8.x4.trans.shared.b16 {%0,%1,%2,%3}, [%4];"
                 : "=r"(r[0]), "=r"(r[1]), "=r"(r[2]), "=r"(r[3]) : "r"(addr));
}
__device__ __forceinline__ float ex2(float x) {
    float r; asm("ex2.approx.f32 %0, %1;" : "=f"(r) : "f"(x)); return r;
}
#define CP16(sa, g) asm volatile("cp.async.cg.shared.global [%0], [%1], 16;" :: "r"(sa), "l"(g) : "memory")
#define CP_COMMIT() asm volatile("cp.async.commit_group;" ::: "memory")
#define CP_WAIT0()  asm volatile("cp.async.wait_group 0;" ::: "memory")

#define SC_L2E 11.541560327111707f   /* 8 * log2(e): bias+scale in exp2 domain */

__device__ __forceinline__ void split_pack(float a, float b, uint32_t& hi, uint32_t& lo) {
    __half ha = __float2half_rn(a), hb = __float2half_rn(b);
    __half la = __float2half_rn(a - __half2float(ha));
    __half lb = __float2half_rn(b - __half2float(hb));
    __half2 H = __halves2half2(ha, hb), L = __halves2half2(la, lb);
    hi = *(uint32_t*)&H;  lo = *(uint32_t*)&L;
}
__device__ __forceinline__ uint32_t pack2h(float a, float b) {
    __half2 H = __halves2half2(__float2half_rn(a), __float2half_rn(b));
    return *(uint32_t*)&H;
}

// ---------------- fused fp32 -> fp16 hi/lo split (float4 units) --------------
__global__ void split_all(const float* __restrict__ x, const float* __restrict__ wa,
                          const float* __restrict__ wp) {
    int i = blockIdx.x * blockDim.x + threadIdx.x;
    const float* s; uint2* hi; uint2* lo; int off;
    if (i < 1048576)      { s = x;  hi = (uint2*)g_xh;  lo = (uint2*)g_xl;  off = i; }
    else if (i < 1835008) { s = wa; hi = (uint2*)g_wah; lo = (uint2*)g_wal; off = i - 1048576; }
    else                  { s = wp; hi = (uint2*)g_wph; lo = (uint2*)g_wpl; off = i - 1835008; }
    float4 v = ((const float4*)s)[off];
    uint2 H, L;
    split_pack(v.x, v.y, H.x, L.x);
    split_pack(v.z, v.w, H.y, L.y);
    hi[off] = H;
    lo[off] = L;
}

// ---------------------------------------------------------------------------
// HMMA fp16x2 GEMM  [R11/R14 shape — frozen]
// ---------------------------------------------------------------------------
#define GEMM_SMEM (2 * 49152)

template<int EPI>
__global__ __launch_bounds__(256, 2)
void gemm_h2(const __half* __restrict__ Ah, const __half* __restrict__ Al,
             const __half* __restrict__ Bh_, const __half* __restrict__ Bl_,
             float* __restrict__ C, int M, int N, int K)
{
    extern __shared__ char smem[];
    const uint32_t sb = smem_u32(smem);
    const int tid = threadIdx.x, lane = tid & 31, wid = tid >> 5;
    const int wm = wid >> 1, wn = wid & 1;
    const int m0 = blockIdx.y * 128, n0 = blockIdx.x * 64;

    const int npass = (EPI == 0) ? 2 : ((n0 < 2048) ? 3 : 1);
    const bool ldAl = (npass == 3);
    const bool ldBl = (npass >= 2);

    auto issue = [&](int buf, int k0) {
        const uint32_t bb = sb + (uint32_t)(buf * 49152);
#pragma unroll
        for (int p = 0; p < 2; p++) {
            if (p == 1 && !ldAl) break;
            const __half* S = p ? Al : Ah;
#pragma unroll
            for (int u = 0; u < 4; u++) {
                int unit = tid + u * 256;
                int r = unit >> 3, sg = unit & 7;
                uint32_t sa = bb + (uint32_t)(p * 16384) + r * 128 + ((sg ^ (r & 7)) << 4);
                CP16(sa, (const void*)(S + (size_t)(m0 + r) * K + k0 + sg * 8));
            }
        }
#pragma unroll
        for (int p = 0; p < 2; p++) {
            if (p == 1 && !ldBl) break;
            const __half* S = p ? Bl_ : Bh_;
#pragma unroll
            for (int u = 0; u < 2; u++) {
                int unit = tid + u * 256;
                int r = unit >> 3, sg = unit & 7;
                uint32_t sa = bb + 32768u + (uint32_t)(p * 8192) + r * 128 + ((sg ^ (r & 7)) << 4);
                CP16(sa, (const void*)(S + (size_t)(n0 + r) * K + k0 + sg * 8));
            }
        }
        CP_COMMIT();
    };

    float acc[2][4][4];
#pragma unroll
    for (int mt = 0; mt < 2; mt++)
#pragma unroll
        for (int nt = 0; nt < 4; nt++)
#pragma unroll
            for (int j = 0; j < 4; j++) acc[mt][nt][j] = 0.f;

    const int NC = K >> 6;
    issue(0, 0);
    for (int kc = 0; kc < NC; kc++) {
        const int buf = kc & 1;
        CP_WAIT0();
        __syncthreads();
        if (kc + 1 < NC) issue(buf ^ 1, (kc + 1) * 64);

        const uint32_t Ab = sb + (uint32_t)(buf * 49152);
        const uint32_t Bb = Ab + 32768u;

#pragma unroll
        for (int ks = 0; ks < 4; ks++) {
            uint32_t Af[2][2][4];
            uint32_t Bf[2][2][4];
#pragma unroll
            for (int p = 0; p < 2; p++) {
                if (p == 0 || ldAl) {
#pragma unroll
                    for (int mt = 0; mt < 2; mt++) {
                        int row = wm * 32 + mt * 16 + (lane & 15);
                        int un = (ks * 2 + (lane >> 4)) ^ (row & 7);
                        ldsm4(Af[p][mt], Ab + (uint32_t)(p * 16384) + row * 128 + un * 16);
                    }
                }
                if (p == 0 || ldBl) {
#pragma unroll
                    for (int g = 0; g < 2; g++) {
                        int row = wn * 32 + g * 16 + (lane & 15);
                        int un = (ks * 2 + (lane >> 4)) ^ (row & 7);
                        ldsm4(Bf[p][g], Bb + (uint32_t)(p * 8192) + row * 128 + un * 16);
                    }
                }
            }
#pragma unroll
            for (int pass = 0; pass < 3; pass++) {
                if (pass >= npass) break;
                const int ap = (pass == 2) ? 1 : 0;
                const int bp = (pass == 1) ? 1 : 0;
#pragma unroll
                for (int mt = 0; mt < 2; mt++)
#pragma unroll
                    for (int g = 0; g < 2; g++) {
                        mma_f16(acc[mt][2 * g],     Af[ap][mt], Bf[bp][g][0], Bf[bp][g][2]);
                        mma_f16(acc[mt][2 * g + 1], Af[ap][mt], Bf[bp][g][1], Bf[bp][g][3]);
                    }
            }
        }
    }

#pragma unroll
    for (int mt = 0; mt < 2; mt++) {
        int r0 = m0 + wm * 32 + mt * 16 + (lane >> 2);
        int r1 = r0 + 8;
#pragma unroll
        for (int nt = 0; nt < 4; nt++) {
            int n = n0 + wn * 32 + nt * 8 + (lane & 3) * 2;
            if (EPI == 0) {
                *(float2*)(C + (size_t)r0 * N + n) = make_float2(acc[mt][nt][0], acc[mt][nt][1]);
                *(float2*)(C + (size_t)r1 * N + n) = make_float2(acc[mt][nt][2], acc[mt][nt][3]);
            } else {
                int which = n >> 10, rem = n & 1023;
                int h = rem >> 6, d = rem & 63;
#pragma unroll
                for (int half_ = 0; half_ < 2; half_++) {
                    int m = half_ ? r1 : r0;
                    float v0 = acc[mt][nt][half_ * 2], v1 = acc[mt][nt][half_ * 2 + 1];
                    int b = m >> 11, t = m & 2047;
                    size_t idx = (((size_t)b * HH + h) * TT + t) * DD + d;
                    if (which < 2) {
                        __half* dh = (which == 0) ? g_qh : g_kh;
                        __half* dl = (which == 0) ? g_ql : g_kl;
                        uint32_t hpk, lpk;
                        split_pack(v0, v1, hpk, lpk);
                        *(uint32_t*)(dh + idx) = hpk;
                        *(uint32_t*)(dl + idx) = lpk;
                    } else {
                        *(uint32_t*)(g_vh + idx) = pack2h(v0, v1);
                    }
                }
            }
        }
    }
}

// ---------------------------------------------------------------------------
// Flash attention on HMMA. CTA: 128 q-rows, 128 threads (4 warps, warp=32 rows).
// K/V fragment loads amortized over 2x rows vs R14. 2 CTAs/SM, 256-reg budget.
// Grid x = tile*2 + b (bias L2 pairing). QK 3-pass, PV 1-pass, exp2 softmax.
// smem: Q hi/lo 32KB + KV double buffer 2 x 24KB = 80KB.
// ---------------------------------------------------------------------------
#define ATTN_SMEM (32768 + 2 * 24576)

__global__ __launch_bounds__(128, 2)
void attn_mma(const float* __restrict__ bias)
{
    extern __shared__ char smem[];
    const uint32_t sb = smem_u32(smem);
    const int tid = threadIdx.x, lane = tid & 31, wid = tid >> 5;
    const int bx = (int)blockIdx.x;
    const int b = bx & 1;
    const int ntx = (int)(gridDim.x >> 1);
    const int t0 = (ntx - 1 - (bx >> 1)) * 128;   // heavy tiles first
    const int h = blockIdx.y;

    const size_t qoff  = ((size_t)(b * HH + h) * TT + t0) * DD;
    const size_t kvoff = (size_t)(b * HH + h) * TT * DD;

    // Q load (hi/lo): 2 parts x 128 rows x 8 segs = 2048 16B units
    {
        const __half* S[2] = {g_qh + qoff, g_ql + qoff};
#pragma unroll
        for (int u = 0; u < 16; u++) {
            int unit = tid + u * 128;
            int p = unit >> 10, rem = unit & 1023;
            int r = rem >> 3, sg = rem & 7;
            uint32_t sa = sb + (uint32_t)(p * 16384) + r * 128 + ((sg ^ (r & 7)) << 4);
            CP16(sa, (const void*)(S[p] + (size_t)r * 64 + sg * 8));
        }
    }
    const __half* kvsrc[3] = {g_kh + kvoff, g_kl + kvoff, g_vh + kvoff};
    auto kv_issue = [&](int buf, int s0) {
        const uint32_t bb = sb + 32768u + (uint32_t)(buf * 24576);
#pragma unroll
        for (int u = 0; u < 12; u++) {
            int unit = tid + u * 128;              // 3 parts x 64 rows x 8 segs
            int p = unit >> 9, rem = unit & 511;
            int r = rem >> 3, sg = rem & 7;
            uint32_t sa = bb + (uint32_t)(p * 8192) + r * 128 + ((sg ^ (r & 7)) << 4);
            CP16(sa, (const void*)(kvsrc[p] + (size_t)(s0 + r) * 64 + sg * 8));
        }
        CP_COMMIT();
    };
    kv_issue(0, 0);

    float m_r[2][2], l_r[2][2];
#pragma unroll
    for (int mt = 0; mt < 2; mt++) { m_r[mt][0] = m_r[mt][1] = -1e30f; l_r[mt][0] = l_r[mt][1] = 0.f; }
    float y[2][8][4];
#pragma unroll
    for (int mt = 0; mt < 2; mt++)
#pragma unroll
        for (int nt = 0; nt < 8; nt++)
#pragma unroll
            for (int j = 0; j < 4; j++) y[mt][nt][j] = 0.f;

    const int wrow = t0 + wid * 32;                  // warp's first q-row
    const int wmax = wrow + 31;
    int r0g[2], r1g[2];
#pragma unroll
    for (int mt = 0; mt < 2; mt++) { r0g[mt] = wrow + mt * 16 + (lane >> 2); r1g[mt] = r0g[mt] + 8; }
    const int ntiles = t0 / 64 + 2;

    for (int it = 0; it < ntiles; it++) {
        CP_WAIT0();
        __syncthreads();
        if (it + 1 < ntiles) kv_issue((it + 1) & 1, (it + 1) * 64);

        const int s0 = it * 64;
        if (s0 <= wmax) {                            // skip tiles above diagonal
            const uint32_t Kb = sb + 32768u + (uint32_t)((it & 1) * 24576);
            const uint32_t Vb = Kb + 16384u;

            // ---- S = Q.K^T ----
            float S[2][8][4];
#pragma unroll
            for (int mt = 0; mt < 2; mt++)
#pragma unroll
                for (int nt = 0; nt < 8; nt++)
#pragma unroll
                    for (int j = 0; j < 4; j++) S[mt][nt][j] = 0.f;

#pragma unroll
            for (int ks = 0; ks < 4; ks++) {
                uint32_t Qf[2][2][4];   // [part][mt]
#pragma unroll
                for (int p = 0; p < 2; p++)
#pragma unroll
                    for (int mt = 0; mt < 2; mt++) {
                        int row = wid * 32 + mt * 16 + (lane & 15);
                        int un = (ks * 2 + (lane >> 4)) ^ (row & 7);
                        ldsm4(Qf[p][mt], sb + (uint32_t)(p * 16384) + row * 128 + un * 16);
                    }
                uint32_t Bf[2][4][4];
#pragma unroll
                for (int p = 0; p < 2; p++)
#pragma unroll
                    for (int g = 0; g < 4; g++) {
                        int row = g * 16 + (lane & 15);
                        int un = (ks * 2 + (lane >> 4)) ^ (row & 7);
                        ldsm4(Bf[p][g], Kb + (uint32_t)(p * 8192) + row * 128 + un * 16);
                    }
#pragma unroll
                for (int pass = 0; pass < 3; pass++) {
                    const int ap = (pass == 2) ? 1 : 0;
                    const int bp = (pass == 1) ? 1 : 0;
#pragma unroll
                    for (int mt = 0; mt < 2; mt++)
#pragma unroll
                        for (int g = 0; g < 4; g++) {
                            mma_f16(S[mt][2 * g],     Qf[ap][mt], Bf[bp][g][0], Bf[bp][g][2]);
                            mma_f16(S[mt][2 * g + 1], Qf[ap][mt], Bf[bp][g][1], Bf[bp][g][3]);
                        }
                }
            }

            // ---- bias + scale (exp2 domain) + causal mask ----
            const bool diag = (it >= ntiles - 2);
#pragma unroll
            for (int mt = 0; mt < 2; mt++) {
                const float* br0 = bias + ((size_t)h * TT + r0g[mt]) * TT + s0 + (lane & 3) * 2;
                const float* br1 = bias + ((size_t)h * TT + r1g[mt]) * TT + s0 + (lane & 3) * 2;
#pragma unroll
                for (int nt = 0; nt < 8; nt++) {
                    float2 b0 = *(const float2*)(br0 + nt * 8);
                    float2 b1 = *(const float2*)(br1 + nt * 8);
                    S[mt][nt][0] = (S[mt][nt][0] + b0.x) * SC_L2E;
                    S[mt][nt][1] = (S[mt][nt][1] + b0.y) * SC_L2E;
                    S[mt][nt][2] = (S[mt][nt][2] + b1.x) * SC_L2E;
                    S[mt][nt][3] = (S[mt][nt][3] + b1.y) * SC_L2E;
                    if (diag) {
                        int cg = s0 + nt * 8 + (lane & 3) * 2;
                        if (cg     > r0g[mt]) S[mt][nt][0] = -1e30f;
                        if (cg + 1 > r0g[mt]) S[mt][nt][1] = -1e30f;
                        if (cg     > r1g[mt]) S[mt][nt][2] = -1e30f;
                        if (cg + 1 > r1g[mt]) S[mt][nt][3] = -1e30f;
                    }
                }
            }

            // ---- online softmax (exp2 domain) + P pack + PV ----
            uint32_t Ph[2][4][4];
#pragma unroll
            for (int mt = 0; mt < 2; mt++) {
                float mx0 = -1e30f, mx1 = -1e30f;
#pragma unroll
                for (int nt = 0; nt < 8; nt++) {
                    mx0 = fmaxf(mx0, fmaxf(S[mt][nt][0], S[mt][nt][1]));
                    mx1 = fmaxf(mx1, fmaxf(S[mt][nt][2], S[mt][nt][3]));
                }
                mx0 = fmaxf(mx0, __shfl_xor_sync(0xFFFFFFFF, mx0, 1));
                mx0 = fmaxf(mx0, __shfl_xor_sync(0xFFFFFFFF, mx0, 2));
                mx1 = fmaxf(mx1, __shfl_xor_sync(0xFFFFFFFF, mx1, 1));
                mx1 = fmaxf(mx1, __shfl_xor_sync(0xFFFFFFFF, mx1, 2));
                float mn0 = fmaxf(m_r[mt][0], mx0), mn1 = fmaxf(m_r[mt][1], mx1);
                float sc0 = ex2(m_r[mt][0] - mn0), sc1 = ex2(m_r[mt][1] - mn1);
                m_r[mt][0] = mn0; m_r[mt][1] = mn1;

                float sum0 = 0.f, sum1 = 0.f;
#pragma unroll
                for (int ks = 0; ks < 4; ks++) {
#pragma unroll
                    for (int half_ = 0; half_ < 2; half_++) {
                        int nt = 2 * ks + half_;
                        float p0 = ex2(S[mt][nt][0] - mn0);
                        float p1 = ex2(S[mt][nt][1] - mn0);
                        float p2 = ex2(S[mt][nt][2] - mn1);
                        float p3 = ex2(S[mt][nt][3] - mn1);
                        sum0 += p0 + p1; sum1 += p2 + p3;
                        Ph[mt][ks][half_ * 2]     = pack2h(p0, p1);
                        Ph[mt][ks][half_ * 2 + 1] = pack2h(p2, p3);
                    }
                }
                sum0 += __shfl_xor_sync(0xFFFFFFFF, sum0, 1);
                sum0 += __shfl_xor_sync(0xFFFFFFFF, sum0, 2);
                sum1 += __shfl_xor_sync(0xFFFFFFFF, sum1, 1);
                sum1 += __shfl_xor_sync(0xFFFFFFFF, sum1, 2);
                l_r[mt][0] = l_r[mt][0] * sc0 + sum0;
                l_r[mt][1] = l_r[mt][1] * sc1 + sum1;
#pragma unroll
                for (int nt = 0; nt < 8; nt++) {
                    y[mt][nt][0] *= sc0; y[mt][nt][1] *= sc0;
                    y[mt][nt][2] *= sc1; y[mt][nt][3] *= sc1;
                }
            }

            // ---- y += P.V  (V frags shared across both m-tiles) ----
#pragma unroll
            for (int ks = 0; ks < 4; ks++) {
                uint32_t Vf[4][4];
#pragma unroll
                for (int dc = 0; dc < 4; dc++) {
                    int row = ks * 16 + (lane & 15);
                    int un = (2 * dc + (lane >> 4)) ^ (row & 7);
                    ldsm4t(Vf[dc], Vb + row * 128 + un * 16);
                }
#pragma unroll
                for (int mt = 0; mt < 2; mt++)
#pragma unroll
                    for (int dc = 0; dc < 4; dc++) {
                        mma_f16(y[mt][2 * dc],     Ph[mt][ks], Vf[dc][0], Vf[dc][1]);
                        mma_f16(y[mt][2 * dc + 1], Ph[mt][ks], Vf[dc][2], Vf[dc][3]);
                    }
            }
        }
    }

    // ---- normalize, store y (fp16 hi only) to g_yh [B*T][C] ----
#pragma unroll
    for (int mt = 0; mt < 2; mt++) {
        float inv0 = 1.f / l_r[mt][0], inv1 = 1.f / l_r[mt][1];
#pragma unroll
        for (int nt = 0; nt < 8; nt++) {
            int col = h * 64 + nt * 8 + (lane & 3) * 2;
            size_t row0 = (size_t)b * TT + r0g[mt];
            size_t row1 = (size_t)b * TT + r1g[mt];
            *(uint32_t*)(g_yh + row0 * CC + col) = pack2h(y[mt][nt][0] * inv0, y[mt][nt][1] * inv0);
            *(uint32_t*)(g_yh + row1 * CC + col) = pack2h(y[mt][nt][2] * inv1, y[mt][nt][3] * inv1);
        }
    }
}

// ---------------------------------------------------------------------------
extern "C" void kernel_launch(void* const* d_in, const int* in_sizes, int n_in,
                              void* d_out, int out_size)
{
    const float* x    = (const float*)d_in[0];   // [B,T,C]
    const float* bias = (const float*)d_in[1];   // [1,H,T,T]
    const float* Wa   = (const float*)d_in[2];   // [3C,C]
    const float* Wp   = (const float*)d_in[3];   // [C,C]
    float* out = (float*)d_out;

    const int M = BB * TT;   // 4096

    void *xh, *xl, *wah, *wal, *wph, *wpl, *yh;
    cudaGetSymbolAddress(&xh, g_xh);   cudaGetSymbolAddress(&xl, g_xl);
    cudaGetSymbolAddress(&wah, g_wah); cudaGetSymbolAddress(&wal, g_wal);
    cudaGetSymbolAddress(&wph, g_wph); cudaGetSymbolAddress(&wpl, g_wpl);
    cudaGetSymbolAddress(&yh, g_yh);

    cudaFuncSetAttribute(gemm_h2<1>, cudaFuncAttributeMaxDynamicSharedMemorySize, GEMM_SMEM);
    cudaFuncSetAttribute(gemm_h2<0>, cudaFuncAttributeMaxDynamicSharedMemorySize, GEMM_SMEM);
    cudaFuncSetAttribute(attn_mma,   cudaFuncAttributeMaxDynamicSharedMemorySize, ATTN_SMEM);

    // 0) fused fp32 -> fp16 hi/lo split of x, W_attn, W_proj (float4 units)
    split_all<<<8192, 256>>>(x, Wa, Wp);

    // 1) QKV projection -> split q/k (3-pass) + v hi (1-pass) in [B,H,T,D]
    gemm_h2<1><<<dim3(3 * CC / 64, M / 128), 256, GEMM_SMEM>>>(
        (const __half*)xh, (const __half*)xl,
        (const __half*)wah, (const __half*)wal, nullptr, M, 3 * CC, CC);

    // 2) flash attention (HMMA, 128-row CTAs / 4 warps, batch-paired) -> y hi
    attn_mma<<<dim3(TT / 128 * BB, HH, 1), 128, ATTN_SMEM>>>(bias);

    // 3) output projection (2-pass: yh*Wh + yh*Wl) -> fp32 out
    gemm_h2<0><<<dim3(CC / 64, M / 128), 256, GEMM_SMEM>>>(
        (const __half*)yh, (const __half*)yh,
        (const __half*)wph, (const __half*)wpl, out, M, CC, CC);
}

// round 16
// speedup vs baseline: 1.1134x; 1.1134x over previous
#include <cuda_runtime.h>
#include <cuda_fp16.h>
#include <math.h>
#include <stdint.h>

#define BB 2
#define TT 2048
#define CC 1024
#define HH 16
#define DD 64

// ---------------- device scratch (allocation-free rule) ----------------
__device__ __half g_xh[4194304],  g_xl[4194304];    // x split        [4096][1024]
__device__ __half g_wah[3145728], g_wal[3145728];   // W_attn split   [3072][1024]
__device__ __half g_wph[1048576], g_wpl[1048576];   // W_proj split   [1024][1024]
__device__ __half g_qh[4194304],  g_ql[4194304];    // q split  [B,H,T,D]
__device__ __half g_kh[4194304],  g_kl[4194304];
__device__ __half g_vh[4194304];                    // v hi only
__device__ __half g_yh[4194304];                    // attn out hi only [4096][1024]

// ---------------- helpers ----------------
__device__ __forceinline__ uint32_t smem_u32(const void* p) {
    uint32_t a;
    asm("{ .reg .u64 t; cvta.to.shared.u64 t, %1; cvt.u32.u64 %0, t; }" : "=r"(a) : "l"(p));
    return a;
}

__device__ __forceinline__ void mma_f16(float* c, const uint32_t* a, uint32_t b0, uint32_t b1) {
    asm volatile(
        "mma.sync.aligned.m16n8k16.row.col.f32.f16.f16.f32 "
        "{%0,%1,%2,%3}, {%4,%5,%6,%7}, {%8,%9}, {%0,%1,%2,%3};\n"
        : "+f"(c[0]), "+f"(c[1]), "+f"(c[2]), "+f"(c[3])
        : "r"(a[0]), "r"(a[1]), "r"(a[2]), "r"(a[3]), "r"(b0), "r"(b1));
}
__device__ __forceinline__ void ldsm4(uint32_t* r, uint32_t addr) {
    asm volatile("ldmatrix.sync.aligned.m8n8.x4.shared.b16 {%0,%1,%2,%3}, [%4];"
                 : "=r"(r[0]), "=r"(r[1]), "=r"(r[2]), "=r"(r[3]) : "r"(addr));
}
__device__ __forceinline__ void ldsm4t(uint32_t* r, uint32_t addr) {
    asm volatile("ldmatrix.sync.aligned.m8n8.x4.trans.shared.b16 {%0,%1,%2,%3}, [%4];"
                 : "=r"(r[0]), "=r"(r[1]), "=r"(r[2]), "=r"(r[3]) : "r"(addr));
}
__device__ __forceinline__ float ex2(float x) {
    float r; asm("ex2.approx.f32 %0, %1;" : "=f"(r) : "f"(x)); return r;
}
#define CP16(sa, g) asm volatile("cp.async.cg.shared.global [%0], [%1], 16;" :: "r"(sa), "l"(g) : "memory")
#define CP_COMMIT() asm volatile("cp.async.commit_group;" ::: "memory")
#define CP_WAIT1()  asm volatile("cp.async.wait_group 1;" ::: "memory")
#define CP_WAIT0()  asm volatile("cp.async.wait_group 0;" ::: "memory")

#define SC_L2E 11.541560327111707f   /* 8 * log2(e): bias+scale in exp2 domain */

__device__ __forceinline__ void split_pack(float a, float b, uint32_t& hi, uint32_t& lo) {
    __half ha = __float2half_rn(a), hb = __float2half_rn(b);
    __half la = __float2half_rn(a - __half2float(ha));
    __half lb = __float2half_rn(b - __half2float(hb));
    __half2 H = __halves2half2(ha, hb), L = __halves2half2(la, lb);
    hi = *(uint32_t*)&H;  lo = *(uint32_t*)&L;
}
__device__ __forceinline__ uint32_t pack2h(float a, float b) {
    __half2 H = __halves2half2(__float2half_rn(a), __float2half_rn(b));
    return *(uint32_t*)&H;
}

// ---------------- fused fp32 -> fp16 hi/lo split (float4 units) --------------
__global__ void split_all(const float* __restrict__ x, const float* __restrict__ wa,
                          const float* __restrict__ wp) {
    int i = blockIdx.x * blockDim.x + threadIdx.x;
    const float* s; uint2* hi; uint2* lo; int off;
    if (i < 1048576)      { s = x;  hi = (uint2*)g_xh;  lo = (uint2*)g_xl;  off = i; }
    else if (i < 1835008) { s = wa; hi = (uint2*)g_wah; lo = (uint2*)g_wal; off = i - 1048576; }
    else                  { s = wp; hi = (uint2*)g_wph; lo = (uint2*)g_wpl; off = i - 1835008; }
    float4 v = ((const float4*)s)[off];
    uint2 H, L;
    split_pack(v.x, v.y, H.x, L.x);
    split_pack(v.z, v.w, H.y, L.y);
    hi[off] = H;
    lo[off] = L;
}

// ---------------------------------------------------------------------------
// HMMA fp16x2 GEMM  [R11/R14 shape]
// CTA tile 128x64, BK=64, 256 threads (8 warps, 4m x 2n, warp 32x32), 2 CTAs/SM.
// EPI=1 (qkv): 2-stage, 48KB buffers; q/k 3-pass split-store, v 1-pass.
// EPI=0 (proj): 3-stage pipeline, 32KB buffers (Ah|Bh|Bl), 2-pass.
// Single barrier per K-chunk: wait; bar; issue(kc+NSTAGE-1); compute.
// ---------------------------------------------------------------------------
#define GEMM_SMEM (2 * 49152)

template<int EPI>
__global__ __launch_bounds__(256, 2)
void gemm_h2(const __half* __restrict__ Ah, const __half* __restrict__ Al,
             const __half* __restrict__ Bh_, const __half* __restrict__ Bl_,
             float* __restrict__ C, int M, int N, int K)
{
    extern __shared__ char smem[];
    const uint32_t sb = smem_u32(smem);
    const int tid = threadIdx.x, lane = tid & 31, wid = tid >> 5;
    const int wm = wid >> 1, wn = wid & 1;
    const int m0 = blockIdx.y * 128, n0 = blockIdx.x * 64;

    const int npass = (EPI == 0) ? 2 : ((n0 < 2048) ? 3 : 1);
    const bool ldAl = (npass == 3);
    const bool ldBl = (npass >= 2);

    constexpr int NSTAGE = (EPI == 0) ? 3 : 2;
    constexpr uint32_t BUFB = (EPI == 0) ? 32768u : 49152u;
    constexpr uint32_t BOFF = (EPI == 0) ? 16384u : 32768u;   // B base within buffer

    auto issue = [&](int buf, int k0) {
        const uint32_t bb = sb + (uint32_t)buf * BUFB;
#pragma unroll
        for (int p = 0; p < 2; p++) {
            if (p == 1 && !ldAl) break;
            const __half* S = p ? Al : Ah;
#pragma unroll
            for (int u = 0; u < 4; u++) {
                int unit = tid + u * 256;
                int r = unit >> 3, sg = unit & 7;
                uint32_t sa = bb + (uint32_t)(p * 16384) + r * 128 + ((sg ^ (r & 7)) << 4);
                CP16(sa, (const void*)(S + (size_t)(m0 + r) * K + k0 + sg * 8));
            }
        }
#pragma unroll
        for (int p = 0; p < 2; p++) {
            if (p == 1 && !ldBl) break;
            const __half* S = p ? Bl_ : Bh_;
#pragma unroll
            for (int u = 0; u < 2; u++) {
                int unit = tid + u * 256;
                int r = unit >> 3, sg = unit & 7;
                uint32_t sa = bb + BOFF + (uint32_t)(p * 8192) + r * 128 + ((sg ^ (r & 7)) << 4);
                CP16(sa, (const void*)(S + (size_t)(n0 + r) * K + k0 + sg * 8));
            }
        }
        CP_COMMIT();
    };

    float acc[2][4][4];
#pragma unroll
    for (int mt = 0; mt < 2; mt++)
#pragma unroll
        for (int nt = 0; nt < 4; nt++)
#pragma unroll
            for (int j = 0; j < 4; j++) acc[mt][nt][j] = 0.f;

    const int NC = K >> 6;
    issue(0, 0);
    if (NSTAGE == 3 && NC > 1) issue(1, 64);

    for (int kc = 0; kc < NC; kc++) {
        const int buf = kc % NSTAGE;
        if (NSTAGE == 3 && kc + 1 < NC) CP_WAIT1();   // kc landed, kc+1 may pend
        else CP_WAIT0();
        __syncthreads();                              // publish + buffer-reuse safety
        if (kc + NSTAGE - 1 < NC) issue((kc + NSTAGE - 1) % NSTAGE, (kc + NSTAGE - 1) * 64);

        const uint32_t Ab = sb + (uint32_t)buf * BUFB;
        const uint32_t Bb = Ab + BOFF;

#pragma unroll
        for (int ks = 0; ks < 4; ks++) {
            uint32_t Af[2][2][4];
            uint32_t Bf[2][2][4];
#pragma unroll
            for (int p = 0; p < 2; p++) {
                if (p == 0 || ldAl) {
#pragma unroll
                    for (int mt = 0; mt < 2; mt++) {
                        int row = wm * 32 + mt * 16 + (lane & 15);
                        int un = (ks * 2 + (lane >> 4)) ^ (row & 7);
                        ldsm4(Af[p][mt], Ab + (uint32_t)(p * 16384) + row * 128 + un * 16);
                    }
                }
                if (p == 0 || ldBl) {
#pragma unroll
                    for (int g = 0; g < 2; g++) {
                        int row = wn * 32 + g * 16 + (lane & 15);
                        int un = (ks * 2 + (lane >> 4)) ^ (row & 7);
                        ldsm4(Bf[p][g], Bb + (uint32_t)(p * 8192) + row * 128 + un * 16);
                    }
                }
            }
#pragma unroll
            for (int pass = 0; pass < 3; pass++) {
                if (pass >= npass) break;
                const int ap = (pass == 2) ? 1 : 0;
                const int bp = (pass == 1) ? 1 : 0;
#pragma unroll
                for (int mt = 0; mt < 2; mt++)
#pragma unroll
                    for (int g = 0; g < 2; g++) {
                        mma_f16(acc[mt][2 * g],     Af[ap][mt], Bf[bp][g][0], Bf[bp][g][2]);
                        mma_f16(acc[mt][2 * g + 1], Af[ap][mt], Bf[bp][g][1], Bf[bp][g][3]);
                    }
            }
        }
    }

#pragma unroll
    for (int mt = 0; mt < 2; mt++) {
        int r0 = m0 + wm * 32 + mt * 16 + (lane >> 2);
        int r1 = r0 + 8;
#pragma unroll
        for (int nt = 0; nt < 4; nt++) {
            int n = n0 + wn * 32 + nt * 8 + (lane & 3) * 2;
            if (EPI == 0) {
                *(float2*)(C + (size_t)r0 * N + n) = make_float2(acc[mt][nt][0], acc[mt][nt][1]);
                *(float2*)(C + (size_t)r1 * N + n) = make_float2(acc[mt][nt][2], acc[mt][nt][3]);
            } else {
                int which = n >> 10, rem = n & 1023;
                int h = rem >> 6, d = rem & 63;
#pragma unroll
                for (int half_ = 0; half_ < 2; half_++) {
                    int m = half_ ? r1 : r0;
                    float v0 = acc[mt][nt][half_ * 2], v1 = acc[mt][nt][half_ * 2 + 1];
                    int b = m >> 11, t = m & 2047;
                    size_t idx = (((size_t)b * HH + h) * TT + t) * DD + d;
                    if (which < 2) {
                        __half* dh = (which == 0) ? g_qh : g_kh;
                        __half* dl = (which == 0) ? g_ql : g_kl;
                        uint32_t hpk, lpk;
                        split_pack(v0, v1, hpk, lpk);
                        *(uint32_t*)(dh + idx) = hpk;
                        *(uint32_t*)(dl + idx) = lpk;
                    } else {
                        *(uint32_t*)(g_vh + idx) = pack2h(v0, v1);
                    }
                }
            }
        }
    }
}

// ---------------------------------------------------------------------------
// Flash attention on HMMA  [exact R14 — best known]:
// CTA: 64 q-rows, 128 threads, 3 CTAs/SM. Grid x = tile*2 + b (bias L2 pair).
// QK 3-pass, PV 1-pass, exp2 softmax, single barrier per tile.
// smem: Q hi/lo 16KB + KV double buffer 2 x 24KB = 64KB.
// ---------------------------------------------------------------------------
#define ATTN_SMEM (16384 + 2 * 24576)

__global__ __launch_bounds__(128, 3)
void attn_mma(const float* __restrict__ bias)
{
    extern __shared__ char smem[];
    const uint32_t sb = smem_u32(smem);
    const int tid = threadIdx.x, lane = tid & 31, wid = tid >> 5;
    const int bx = (int)blockIdx.x;
    const int b = bx & 1;
    const int ntx = (int)(gridDim.x >> 1);
    const int t0 = (ntx - 1 - (bx >> 1)) * 64;   // heavy tiles first
    const int h = blockIdx.y;

    const size_t qoff  = ((size_t)(b * HH + h) * TT + t0) * DD;
    const size_t kvoff = (size_t)(b * HH + h) * TT * DD;

    // Q load (hi/lo) — joins KV(0)'s cp.async group
    {
        const __half* S[2] = {g_qh + qoff, g_ql + qoff};
#pragma unroll
        for (int p = 0; p < 2; p++)
#pragma unroll
            for (int u = 0; u < 4; u++) {
                int unit = tid + u * 128;          // 0..511
                int r = unit >> 3, sg = unit & 7;
                uint32_t sa = sb + (uint32_t)(p * 8192) + r * 128 + ((sg ^ (r & 7)) << 4);
                CP16(sa, (const void*)(S[p] + (size_t)r * 64 + sg * 8));
            }
    }
    const __half* kvsrc[3] = {g_kh + kvoff, g_kl + kvoff, g_vh + kvoff};
    auto kv_issue = [&](int buf, int s0) {
        const uint32_t bb = sb + 16384u + (uint32_t)(buf * 24576);
#pragma unroll
        for (int u = 0; u < 12; u++) {
            int unit = tid + u * 128;              // 3 parts x 64 rows x 8 segs
            int p = unit >> 9, rem = unit & 511;
            int r = rem >> 3, sg = rem & 7;
            uint32_t sa = bb + (uint32_t)(p * 8192) + r * 128 + ((sg ^ (r & 7)) << 4);
            CP16(sa, (const void*)(kvsrc[p] + (size_t)(s0 + r) * 64 + sg * 8));
        }
        CP_COMMIT();
    };
    kv_issue(0, 0);

    float m0r = -1e30f, m1r = -1e30f, l0r = 0.f, l1r = 0.f;
    float y[8][4];
#pragma unroll
    for (int nt = 0; nt < 8; nt++)
#pragma unroll
        for (int j = 0; j < 4; j++) y[nt][j] = 0.f;

    const int r0g = t0 + wid * 16 + (lane >> 2);
    const int r1g = r0g + 8;
    const int ntiles = t0 / 64 + 1;
    const float* brow0 = bias + ((size_t)h * TT + r0g) * TT + (lane & 3) * 2;
    const float* brow1 = bias + ((size_t)h * TT + r1g) * TT + (lane & 3) * 2;

    for (int it = 0; it < ntiles; it++) {
        CP_WAIT0();          // KV(it) landed (only pending group)
        __syncthreads();     // publish + all warps done with buf^1 reads
        if (it + 1 < ntiles) kv_issue((it + 1) & 1, (it + 1) * 64);

        // bias prefetch (gmem latency hidden under S MMAs)
        float2 bv0[8], bv1[8];
#pragma unroll
        for (int nt = 0; nt < 8; nt++) {
            bv0[nt] = *(const float2*)(brow0 + it * 64 + nt * 8);
            bv1[nt] = *(const float2*)(brow1 + it * 64 + nt * 8);
        }

        const uint32_t Kb = sb + 16384u + (uint32_t)((it & 1) * 24576);
        const uint32_t Vb = Kb + 16384u;

        // ---- S = Q.K^T ----
        float S[8][4];
#pragma unroll
        for (int nt = 0; nt < 8; nt++)
#pragma unroll
            for (int j = 0; j < 4; j++) S[nt][j] = 0.f;

#pragma unroll
        for (int ks = 0; ks < 4; ks++) {
            uint32_t Qf[2][4];
#pragma unroll
            for (int p = 0; p < 2; p++) {
                int row = wid * 16 + (lane & 15);
                int un = (ks * 2 + (lane >> 4)) ^ (row & 7);
                ldsm4(Qf[p], sb + (uint32_t)(p * 8192) + row * 128 + un * 16);
            }
            uint32_t Bf[2][4][4];
#pragma unroll
            for (int p = 0; p < 2; p++)
#pragma unroll
                for (int g = 0; g < 4; g++) {
                    int row = g * 16 + (lane & 15);
                    int un = (ks * 2 + (lane >> 4)) ^ (row & 7);
                    ldsm4(Bf[p][g], Kb + (uint32_t)(p * 8192) + row * 128 + un * 16);
                }
#pragma unroll
            for (int pass = 0; pass < 3; pass++) {
                const int ap = (pass == 2) ? 1 : 0;
                const int bp = (pass == 1) ? 1 : 0;
#pragma unroll
                for (int g = 0; g < 4; g++) {
                    mma_f16(S[2 * g],     Qf[ap], Bf[bp][g][0], Bf[bp][g][2]);
                    mma_f16(S[2 * g + 1], Qf[ap], Bf[bp][g][1], Bf[bp][g][3]);
                }
            }
        }

        // ---- bias + scale (exp2 domain) + causal mask ----
        const bool diag = (it == ntiles - 1);
#pragma unroll
        for (int nt = 0; nt < 8; nt++) {
            S[nt][0] = (S[nt][0] + bv0[nt].x) * SC_L2E;
            S[nt][1] = (S[nt][1] + bv0[nt].y) * SC_L2E;
            S[nt][2] = (S[nt][2] + bv1[nt].x) * SC_L2E;
            S[nt][3] = (S[nt][3] + bv1[nt].y) * SC_L2E;
            if (diag) {
                int cg = it * 64 + nt * 8 + (lane & 3) * 2;
                if (cg     > r0g) S[nt][0] = -1e30f;
                if (cg + 1 > r0g) S[nt][1] = -1e30f;
                if (cg     > r1g) S[nt][2] = -1e30f;
                if (cg + 1 > r1g) S[nt][3] = -1e30f;
            }
        }

        // ---- online softmax (exp2 domain) ----
        float mx0 = -1e30f, mx1 = -1e30f;
#pragma unroll
        for (int nt = 0; nt < 8; nt++) {
            mx0 = fmaxf(mx0, fmaxf(S[nt][0], S[nt][1]));
            mx1 = fmaxf(mx1, fmaxf(S[nt][2], S[nt][3]));
        }
        mx0 = fmaxf(mx0, __shfl_xor_sync(0xFFFFFFFF, mx0, 1));
        mx0 = fmaxf(mx0, __shfl_xor_sync(0xFFFFFFFF, mx0, 2));
        mx1 = fmaxf(mx1, __shfl_xor_sync(0xFFFFFFFF, mx1, 1));
        mx1 = fmaxf(mx1, __shfl_xor_sync(0xFFFFFFFF, mx1, 2));
        float mn0 = fmaxf(m0r, mx0), mn1 = fmaxf(m1r, mx1);
        float sc0 = ex2(m0r - mn0), sc1 = ex2(m1r - mn1);
        m0r = mn0; m1r = mn1;

        float sum0 = 0.f, sum1 = 0.f;
        uint32_t Ph[4][4];
#pragma unroll
        for (int ks = 0; ks < 4; ks++) {
#pragma unroll
            for (int half_ = 0; half_ < 2; half_++) {
                int nt = 2 * ks + half_;
                float p0 = ex2(S[nt][0] - mn0);
                float p1 = ex2(S[nt][1] - mn0);
                float p2 = ex2(S[nt][2] - mn1);
                float p3 = ex2(S[nt][3] - mn1);
                sum0 += p0 + p1; sum1 += p2 + p3;
                Ph[ks][half_ * 2]     = pack2h(p0, p1);
                Ph[ks][half_ * 2 + 1] = pack2h(p2, p3);
            }
        }
        sum0 += __shfl_xor_sync(0xFFFFFFFF, sum0, 1);
        sum0 += __shfl_xor_sync(0xFFFFFFFF, sum0, 2);
        sum1 += __shfl_xor_sync(0xFFFFFFFF, sum1, 1);
        sum1 += __shfl_xor_sync(0xFFFFFFFF, sum1, 2);
        l0r = l0r * sc0 + sum0;
        l1r = l1r * sc1 + sum1;
#pragma unroll
        for (int nt = 0; nt < 8; nt++) {
            y[nt][0] *= sc0; y[nt][1] *= sc0;
            y[nt][2] *= sc1; y[nt][3] *= sc1;
        }

        // ---- y += P.V  (1 pass: Ph*Vh) ----
#pragma unroll
        for (int ks = 0; ks < 4; ks++) {
            uint32_t Vf[4][4];
#pragma unroll
            for (int dc = 0; dc < 4; dc++) {
                int row = ks * 16 + (lane & 15);
                int un = (2 * dc + (lane >> 4)) ^ (row & 7);
                ldsm4t(Vf[dc], Vb + row * 128 + un * 16);
            }
#pragma unroll
            for (int dc = 0; dc < 4; dc++) {
                mma_f16(y[2 * dc],     Ph[ks], Vf[dc][0], Vf[dc][1]);
                mma_f16(y[2 * dc + 1], Ph[ks], Vf[dc][2], Vf[dc][3]);
            }
        }
    }

    // ---- normalize, store y (fp16 hi only) to g_yh [B*T][C] ----
    float inv0 = 1.f / l0r, inv1 = 1.f / l1r;
#pragma unroll
    for (int nt = 0; nt < 8; nt++) {
        int col = h * 64 + nt * 8 + (lane & 3) * 2;
        size_t row0 = (size_t)b * TT + r0g;
        size_t row1 = (size_t)b * TT + r1g;
        *(uint32_t*)(g_yh + row0 * CC + col) = pack2h(y[nt][0] * inv0, y[nt][1] * inv0);
        *(uint32_t*)(g_yh + row1 * CC + col) = pack2h(y[nt][2] * inv1, y[nt][3] * inv1);
    }
}

// ---------------------------------------------------------------------------
extern "C" void kernel_launch(void* const* d_in, const int* in_sizes, int n_in,
                              void* d_out, int out_size)
{
    const float* x    = (const float*)d_in[0];   // [B,T,C]
    const float* bias = (const float*)d_in[1];   // [1,H,T,T]
    const float* Wa   = (const float*)d_in[2];   // [3C,C]
    const float* Wp   = (const float*)d_in[3];   // [C,C]
    float* out = (float*)d_out;

    const int M = BB * TT;   // 4096

    void *xh, *xl, *wah, *wal, *wph, *wpl, *yh;
    cudaGetSymbolAddress(&xh, g_xh);   cudaGetSymbolAddress(&xl, g_xl);
    cudaGetSymbolAddress(&wah, g_wah); cudaGetSymbolAddress(&wal, g_wal);
    cudaGetSymbolAddress(&wph, g_wph); cudaGetSymbolAddress(&wpl, g_wpl);
    cudaGetSymbolAddress(&yh, g_yh);

    cudaFuncSetAttribute(gemm_h2<1>, cudaFuncAttributeMaxDynamicSharedMemorySize, GEMM_SMEM);
    cudaFuncSetAttribute(gemm_h2<0>, cudaFuncAttributeMaxDynamicSharedMemorySize, GEMM_SMEM);
    cudaFuncSetAttribute(attn_mma,   cudaFuncAttributeMaxDynamicSharedMemorySize, ATTN_SMEM);

    // 0) fused fp32 -> fp16 hi/lo split of x, W_attn, W_proj (float4 units)
    split_all<<<8192, 256>>>(x, Wa, Wp);

    // 1) QKV projection -> split q/k (3-pass) + v hi (1-pass) in [B,H,T,D]
    gemm_h2<1><<<dim3(3 * CC / 64, M / 128), 256, GEMM_SMEM>>>(
        (const __half*)xh, (const __half*)xl,
        (const __half*)wah, (const __half*)wal, nullptr, M, 3 * CC, CC);

    // 2) flash attention (HMMA, 64-row CTAs, 3/SM; batch-paired grid) -> y hi
    attn_mma<<<dim3(TT / 64 * BB, HH, 1), 128, ATTN_SMEM>>>(bias);

    // 3) output projection (2-pass, 3-stage pipeline) -> fp32 out
    gemm_h2<0><<<dim3(CC / 64, M / 128), 256, GEMM_SMEM>>>(
        (const __half*)yh, (const __half*)yh,
        (const __half*)wph, (const __half*)wpl, out, M, CC, CC);
}

// round 17
// speedup vs baseline: 1.1237x; 1.0092x over previous
#include <cuda_runtime.h>
#include <cuda_fp16.h>
#include <math.h>
#include <stdint.h>

#define BB 2
#define TT 2048
#define CC 1024
#define HH 16
#define DD 64

// ---------------- device scratch (allocation-free rule) ----------------
__device__ __half g_xh[4194304],  g_xl[4194304];    // x split        [4096][1024]
__device__ __half g_wah[3145728], g_wal[3145728];   // W_attn split   [3072][1024]
__device__ __half g_wph[1048576], g_wpl[1048576];   // W_proj split   [1024][1024]
__device__ __half g_qh[4194304],  g_ql[4194304];    // q split  [B,H,T,D]
__device__ __half g_kh[4194304],  g_kl[4194304];
__device__ __half g_vh[4194304];                    // v hi only
__device__ __half g_yh[4194304];                    // attn out hi only [4096][1024]

// ---------------- helpers ----------------
__device__ __forceinline__ uint32_t smem_u32(const void* p) {
    uint32_t a;
    asm("{ .reg .u64 t; cvta.to.shared.u64 t, %1; cvt.u32.u64 %0, t; }" : "=r"(a) : "l"(p));
    return a;
}

__device__ __forceinline__ void mma_f16(float* c, const uint32_t* a, uint32_t b0, uint32_t b1) {
    asm volatile(
        "mma.sync.aligned.m16n8k16.row.col.f32.f16.f16.f32 "
        "{%0,%1,%2,%3}, {%4,%5,%6,%7}, {%8,%9}, {%0,%1,%2,%3};\n"
        : "+f"(c[0]), "+f"(c[1]), "+f"(c[2]), "+f"(c[3])
        : "r"(a[0]), "r"(a[1]), "r"(a[2]), "r"(a[3]), "r"(b0), "r"(b1));
}
__device__ __forceinline__ void ldsm4(uint32_t* r, uint32_t addr) {
    asm volatile("ldmatrix.sync.aligned.m8n8.x4.shared.b16 {%0,%1,%2,%3}, [%4];"
                 : "=r"(r[0]), "=r"(r[1]), "=r"(r[2]), "=r"(r[3]) : "r"(addr));
}
__device__ __forceinline__ void ldsm4t(uint32_t* r, uint32_t addr) {
    asm volatile("ldmatrix.sync.aligned.m8n8.x4.trans.shared.b16 {%0,%1,%2,%3}, [%4];"
                 : "=r"(r[0]), "=r"(r[1]), "=r"(r[2]), "=r"(r[3]) : "r"(addr));
}
__device__ __forceinline__ float ex2(float x) {
    float r; asm("ex2.approx.f32 %0, %1;" : "=f"(r) : "f"(x)); return r;
}
#define CP16(sa, g) asm volatile("cp.async.cg.shared.global [%0], [%1], 16;" :: "r"(sa), "l"(g) : "memory")
#define CP_COMMIT() asm volatile("cp.async.commit_group;" ::: "memory")
#define CP_WAIT0()  asm volatile("cp.async.wait_group 0;" ::: "memory")

#define SC_L2E 11.541560327111707f   /* 8 * log2(e): bias+scale in exp2 domain */

__device__ __forceinline__ void split_pack(float a, float b, uint32_t& hi, uint32_t& lo) {
    __half ha = __float2half_rn(a), hb = __float2half_rn(b);
    __half la = __float2half_rn(a - __half2float(ha));
    __half lb = __float2half_rn(b - __half2float(hb));
    __half2 H = __halves2half2(ha, hb), L = __halves2half2(la, lb);
    hi = *(uint32_t*)&H;  lo = *(uint32_t*)&L;
}
__device__ __forceinline__ uint32_t pack2h(float a, float b) {
    __half2 H = __halves2half2(__float2half_rn(a), __float2half_rn(b));
    return *(uint32_t*)&H;
}

// ---------------- fused fp32 -> fp16 hi/lo split (float4 units) --------------
__global__ void split_all(const float* __restrict__ x, const float* __restrict__ wa,
                          const float* __restrict__ wp) {
    int i = blockIdx.x * blockDim.x + threadIdx.x;
    const float* s; uint2* hi; uint2* lo; int off;
    if (i < 1048576)      { s = x;  hi = (uint2*)g_xh;  lo = (uint2*)g_xl;  off = i; }
    else if (i < 1835008) { s = wa; hi = (uint2*)g_wah; lo = (uint2*)g_wal; off = i - 1048576; }
    else                  { s = wp; hi = (uint2*)g_wph; lo = (uint2*)g_wpl; off = i - 1835008; }
    float4 v = ((const float4*)s)[off];
    uint2 H, L;
    split_pack(v.x, v.y, H.x, L.x);
    split_pack(v.z, v.w, H.y, L.y);
    hi[off] = H;
    lo[off] = L;
}

// ---------------------------------------------------------------------------
// HMMA fp16x2 GEMM  [R11/R14 shape — frozen]
// CTA tile 128x64, BK=64, 256 threads (8 warps, 4m x 2n, warp 32x32), 2 CTAs/SM.
// Single barrier per K-chunk: wait; bar; issue(next); compute.
// EPI=0 (proj): 2-pass.  EPI=1 (qkv): q/k 3-pass split-store, v 1-pass.
// ---------------------------------------------------------------------------
#define GEMM_SMEM (2 * 49152)

template<int EPI>
__global__ __launch_bounds__(256, 2)
void gemm_h2(const __half* __restrict__ Ah, const __half* __restrict__ Al,
             const __half* __restrict__ Bh_, const __half* __restrict__ Bl_,
             float* __restrict__ C, int M, int N, int K)
{
    extern __shared__ char smem[];
    const uint32_t sb = smem_u32(smem);
    const int tid = threadIdx.x, lane = tid & 31, wid = tid >> 5;
    const int wm = wid >> 1, wn = wid & 1;
    const int m0 = blockIdx.y * 128, n0 = blockIdx.x * 64;

    const int npass = (EPI == 0) ? 2 : ((n0 < 2048) ? 3 : 1);
    const bool ldAl = (npass == 3);
    const bool ldBl = (npass >= 2);

    auto issue = [&](int buf, int k0) {
        const uint32_t bb = sb + (uint32_t)(buf * 49152);
#pragma unroll
        for (int p = 0; p < 2; p++) {
            if (p == 1 && !ldAl) break;
            const __half* S = p ? Al : Ah;
#pragma unroll
            for (int u = 0; u < 4; u++) {
                int unit = tid + u * 256;
                int r = unit >> 3, sg = unit & 7;
                uint32_t sa = bb + (uint32_t)(p * 16384) + r * 128 + ((sg ^ (r & 7)) << 4);
                CP16(sa, (const void*)(S + (size_t)(m0 + r) * K + k0 + sg * 8));
            }
        }
#pragma unroll
        for (int p = 0; p < 2; p++) {
            if (p == 1 && !ldBl) break;
            const __half* S = p ? Bl_ : Bh_;
#pragma unroll
            for (int u = 0; u < 2; u++) {
                int unit = tid + u * 256;
                int r = unit >> 3, sg = unit & 7;
                uint32_t sa = bb + 32768u + (uint32_t)(p * 8192) + r * 128 + ((sg ^ (r & 7)) << 4);
                CP16(sa, (const void*)(S + (size_t)(n0 + r) * K + k0 + sg * 8));
            }
        }
        CP_COMMIT();
    };

    float acc[2][4][4];
#pragma unroll
    for (int mt = 0; mt < 2; mt++)
#pragma unroll
        for (int nt = 0; nt < 4; nt++)
#pragma unroll
            for (int j = 0; j < 4; j++) acc[mt][nt][j] = 0.f;

    const int NC = K >> 6;
    issue(0, 0);
    for (int kc = 0; kc < NC; kc++) {
        const int buf = kc & 1;
        CP_WAIT0();
        __syncthreads();
        if (kc + 1 < NC) issue(buf ^ 1, (kc + 1) * 64);

        const uint32_t Ab = sb + (uint32_t)(buf * 49152);
        const uint32_t Bb = Ab + 32768u;

#pragma unroll
        for (int ks = 0; ks < 4; ks++) {
            uint32_t Af[2][2][4];
            uint32_t Bf[2][2][4];
#pragma unroll
            for (int p = 0; p < 2; p++) {
                if (p == 0 || ldAl) {
#pragma unroll
                    for (int mt = 0; mt < 2; mt++) {
                        int row = wm * 32 + mt * 16 + (lane & 15);
                        int un = (ks * 2 + (lane >> 4)) ^ (row & 7);
                        ldsm4(Af[p][mt], Ab + (uint32_t)(p * 16384) + row * 128 + un * 16);
                    }
                }
                if (p == 0 || ldBl) {
#pragma unroll
                    for (int g = 0; g < 2; g++) {
                        int row = wn * 32 + g * 16 + (lane & 15);
                        int un = (ks * 2 + (lane >> 4)) ^ (row & 7);
                        ldsm4(Bf[p][g], Bb + (uint32_t)(p * 8192) + row * 128 + un * 16);
                    }
                }
            }
#pragma unroll
            for (int pass = 0; pass < 3; pass++) {
                if (pass >= npass) break;
                const int ap = (pass == 2) ? 1 : 0;
                const int bp = (pass == 1) ? 1 : 0;
#pragma unroll
                for (int mt = 0; mt < 2; mt++)
#pragma unroll
                    for (int g = 0; g < 2; g++) {
                        mma_f16(acc[mt][2 * g],     Af[ap][mt], Bf[bp][g][0], Bf[bp][g][2]);
                        mma_f16(acc[mt][2 * g + 1], Af[ap][mt], Bf[bp][g][1], Bf[bp][g][3]);
                    }
            }
        }
    }

#pragma unroll
    for (int mt = 0; mt < 2; mt++) {
        int r0 = m0 + wm * 32 + mt * 16 + (lane >> 2);
        int r1 = r0 + 8;
#pragma unroll
        for (int nt = 0; nt < 4; nt++) {
            int n = n0 + wn * 32 + nt * 8 + (lane & 3) * 2;
            if (EPI == 0) {
                *(float2*)(C + (size_t)r0 * N + n) = make_float2(acc[mt][nt][0], acc[mt][nt][1]);
                *(float2*)(C + (size_t)r1 * N + n) = make_float2(acc[mt][nt][2], acc[mt][nt][3]);
            } else {
                int which = n >> 10, rem = n & 1023;
                int h = rem >> 6, d = rem & 63;
#pragma unroll
                for (int half_ = 0; half_ < 2; half_++) {
                    int m = half_ ? r1 : r0;
                    float v0 = acc[mt][nt][half_ * 2], v1 = acc[mt][nt][half_ * 2 + 1];
                    int b = m >> 11, t = m & 2047;
                    size_t idx = (((size_t)b * HH + h) * TT + t) * DD + d;
                    if (which < 2) {
                        __half* dh = (which == 0) ? g_qh : g_kh;
                        __half* dl = (which == 0) ? g_ql : g_kl;
                        uint32_t hpk, lpk;
                        split_pack(v0, v1, hpk, lpk);
                        *(uint32_t*)(dh + idx) = hpk;
                        *(uint32_t*)(dl + idx) = lpk;
                    } else {
                        *(uint32_t*)(g_vh + idx) = pack2h(v0, v1);
                    }
                }
            }
        }
    }
}

// ---------------------------------------------------------------------------
// Flash attention on HMMA  [R14 core + latency micro-opts]:
// CTA: 64 q-rows, 128 threads, 3 CTAs/SM. Grid x = tile*2 + b (bias L2 pair).
// Bias prefetch hoisted ABOVE the cp.async wait (full-tile latency cover).
// Tree-shaped max/sum reductions (halved serial chains).
// QK 3-pass, PV 1-pass, exp2 softmax, single barrier per tile.
// smem: Q hi/lo 16KB + KV double buffer 2 x 24KB = 64KB.
// ---------------------------------------------------------------------------
#define ATTN_SMEM (16384 + 2 * 24576)

__global__ __launch_bounds__(128, 3)
void attn_mma(const float* __restrict__ bias)
{
    extern __shared__ char smem[];
    const uint32_t sb = smem_u32(smem);
    const int tid = threadIdx.x, lane = tid & 31, wid = tid >> 5;
    const int bx = (int)blockIdx.x;
    const int b = bx & 1;
    const int ntx = (int)(gridDim.x >> 1);
    const int t0 = (ntx - 1 - (bx >> 1)) * 64;   // heavy tiles first
    const int h = blockIdx.y;

    const size_t qoff  = ((size_t)(b * HH + h) * TT + t0) * DD;
    const size_t kvoff = (size_t)(b * HH + h) * TT * DD;

    // Q load (hi/lo) — joins KV(0)'s cp.async group
    {
        const __half* S[2] = {g_qh + qoff, g_ql + qoff};
#pragma unroll
        for (int p = 0; p < 2; p++)
#pragma unroll
            for (int u = 0; u < 4; u++) {
                int unit = tid + u * 128;          // 0..511
                int r = unit >> 3, sg = unit & 7;
                uint32_t sa = sb + (uint32_t)(p * 8192) + r * 128 + ((sg ^ (r & 7)) << 4);
                CP16(sa, (const void*)(S[p] + (size_t)r * 64 + sg * 8));
            }
    }
    const __half* kvsrc[3] = {g_kh + kvoff, g_kl + kvoff, g_vh + kvoff};
    auto kv_issue = [&](int buf, int s0) {
        const uint32_t bb = sb + 16384u + (uint32_t)(buf * 24576);
#pragma unroll
        for (int u = 0; u < 12; u++) {
            int unit = tid + u * 128;              // 3 parts x 64 rows x 8 segs
            int p = unit >> 9, rem = unit & 511;
            int r = rem >> 3, sg = rem & 7;
            uint32_t sa = bb + (uint32_t)(p * 8192) + r * 128 + ((sg ^ (r & 7)) << 4);
            CP16(sa, (const void*)(kvsrc[p] + (size_t)(s0 + r) * 64 + sg * 8));
        }
        CP_COMMIT();
    };
    kv_issue(0, 0);

    float m0r = -1e30f, m1r = -1e30f, l0r = 0.f, l1r = 0.f;
    float y[8][4];
#pragma unroll
    for (int nt = 0; nt < 8; nt++)
#pragma unroll
        for (int j = 0; j < 4; j++) y[nt][j] = 0.f;

    const int r0g = t0 + wid * 16 + (lane >> 2);
    const int r1g = r0g + 8;
    const int ntiles = t0 / 64 + 1;
    const float* brow0 = bias + ((size_t)h * TT + r0g) * TT + (lane & 3) * 2;
    const float* brow1 = bias + ((size_t)h * TT + r1g) * TT + (lane & 3) * 2;

    for (int it = 0; it < ntiles; it++) {
        // bias prefetch BEFORE the wait/barrier: loads are smem-independent,
        // so their gmem latency is covered by the whole tile body.
        float2 bv0[8], bv1[8];
#pragma unroll
        for (int nt = 0; nt < 8; nt++) {
            bv0[nt] = *(const float2*)(brow0 + it * 64 + nt * 8);
            bv1[nt] = *(const float2*)(brow1 + it * 64 + nt * 8);
        }

        CP_WAIT0();          // KV(it) landed (only pending group)
        __syncthreads();     // publish + all warps done with buf^1 reads
        if (it + 1 < ntiles) kv_issue((it + 1) & 1, (it + 1) * 64);

        const uint32_t Kb = sb + 16384u + (uint32_t)((it & 1) * 24576);
        const uint32_t Vb = Kb + 16384u;

        // ---- S = Q.K^T ----
        float S[8][4];
#pragma unroll
        for (int nt = 0; nt < 8; nt++)
#pragma unroll
            for (int j = 0; j < 4; j++) S[nt][j] = 0.f;

#pragma unroll
        for (int ks = 0; ks < 4; ks++) {
            uint32_t Qf[2][4];
#pragma unroll
            for (int p = 0; p < 2; p++) {
                int row = wid * 16 + (lane & 15);
                int un = (ks * 2 + (lane >> 4)) ^ (row & 7);
                ldsm4(Qf[p], sb + (uint32_t)(p * 8192) + row * 128 + un * 16);
            }
            uint32_t Bf[2][4][4];
#pragma unroll
            for (int p = 0; p < 2; p++)
#pragma unroll
                for (int g = 0; g < 4; g++) {
                    int row = g * 16 + (lane & 15);
                    int un = (ks * 2 + (lane >> 4)) ^ (row & 7);
                    ldsm4(Bf[p][g], Kb + (uint32_t)(p * 8192) + row * 128 + un * 16);
                }
#pragma unroll
            for (int pass = 0; pass < 3; pass++) {
                const int ap = (pass == 2) ? 1 : 0;
                const int bp = (pass == 1) ? 1 : 0;
#pragma unroll
                for (int g = 0; g < 4; g++) {
                    mma_f16(S[2 * g],     Qf[ap], Bf[bp][g][0], Bf[bp][g][2]);
                    mma_f16(S[2 * g + 1], Qf[ap], Bf[bp][g][1], Bf[bp][g][3]);
                }
            }
        }

        // ---- bias + scale (exp2 domain) + causal mask ----
        const bool diag = (it == ntiles - 1);
#pragma unroll
        for (int nt = 0; nt < 8; nt++) {
            S[nt][0] = (S[nt][0] + bv0[nt].x) * SC_L2E;
            S[nt][1] = (S[nt][1] + bv0[nt].y) * SC_L2E;
            S[nt][2] = (S[nt][2] + bv1[nt].x) * SC_L2E;
            S[nt][3] = (S[nt][3] + bv1[nt].y) * SC_L2E;
            if (diag) {
                int cg = it * 64 + nt * 8 + (lane & 3) * 2;
                if (cg     > r0g) S[nt][0] = -1e30f;
                if (cg + 1 > r0g) S[nt][1] = -1e30f;
                if (cg     > r1g) S[nt][2] = -1e30f;
                if (cg + 1 > r1g) S[nt][3] = -1e30f;
            }
        }

        // ---- online softmax (exp2 domain), tree reductions ----
        float ma0 = -1e30f, mb0 = -1e30f, ma1 = -1e30f, mb1 = -1e30f;
#pragma unroll
        for (int nt = 0; nt < 8; nt += 2) {
            ma0 = fmaxf(ma0, fmaxf(S[nt][0],     S[nt][1]));
            ma1 = fmaxf(ma1, fmaxf(S[nt][2],     S[nt][3]));
            mb0 = fmaxf(mb0, fmaxf(S[nt + 1][0], S[nt + 1][1]));
            mb1 = fmaxf(mb1, fmaxf(S[nt + 1][2], S[nt + 1][3]));
        }
        float mx0 = fmaxf(ma0, mb0), mx1 = fmaxf(ma1, mb1);
        mx0 = fmaxf(mx0, __shfl_xor_sync(0xFFFFFFFF, mx0, 1));
        mx0 = fmaxf(mx0, __shfl_xor_sync(0xFFFFFFFF, mx0, 2));
        mx1 = fmaxf(mx1, __shfl_xor_sync(0xFFFFFFFF, mx1, 1));
        mx1 = fmaxf(mx1, __shfl_xor_sync(0xFFFFFFFF, mx1, 2));
        float mn0 = fmaxf(m0r, mx0), mn1 = fmaxf(m1r, mx1);
        float sc0 = ex2(m0r - mn0), sc1 = ex2(m1r - mn1);
        m0r = mn0; m1r = mn1;

        float s0a = 0.f, s0b = 0.f, s1a = 0.f, s1b = 0.f;
        uint32_t Ph[4][4];
#pragma unroll
        for (int ks = 0; ks < 4; ks++) {
#pragma unroll
            for (int half_ = 0; half_ < 2; half_++) {
                int nt = 2 * ks + half_;
                float p0 = ex2(S[nt][0] - mn0);
                float p1 = ex2(S[nt][1] - mn0);
                float p2 = ex2(S[nt][2] - mn1);
                float p3 = ex2(S[nt][3] - mn1);
                if (ks < 2) { s0a += p0 + p1; s1a += p2 + p3; }
                else        { s0b += p0 + p1; s1b += p2 + p3; }
                Ph[ks][half_ * 2]     = pack2h(p0, p1);
                Ph[ks][half_ * 2 + 1] = pack2h(p2, p3);
            }
        }
        float sum0 = s0a + s0b, sum1 = s1a + s1b;
        sum0 += __shfl_xor_sync(0xFFFFFFFF, sum0, 1);
        sum0 += __shfl_xor_sync(0xFFFFFFFF, sum0, 2);
        sum1 += __shfl_xor_sync(0xFFFFFFFF, sum1, 1);
        sum1 += __shfl_xor_sync(0xFFFFFFFF, sum1, 2);
        l0r = l0r * sc0 + sum0;
        l1r = l1r * sc1 + sum1;
#pragma unroll
        for (int nt = 0; nt < 8; nt++) {
            y[nt][0] *= sc0; y[nt][1] *= sc0;
            y[nt][2] *= sc1; y[nt][3] *= sc1;
        }

        // ---- y += P.V  (1 pass: Ph*Vh) ----
#pragma unroll
        for (int ks = 0; ks < 4; ks++) {
            uint32_t Vf[4][4];
#pragma unroll
            for (int dc = 0; dc < 4; dc++) {
                int row = ks * 16 + (lane & 15);
                int un = (2 * dc + (lane >> 4)) ^ (row & 7);
                ldsm4t(Vf[dc], Vb + row * 128 + un * 16);
            }
#pragma unroll
            for (int dc = 0; dc < 4; dc++) {
                mma_f16(y[2 * dc],     Ph[ks], Vf[dc][0], Vf[dc][1]);
                mma_f16(y[2 * dc + 1], Ph[ks], Vf[dc][2], Vf[dc][3]);
            }
        }
    }

    // ---- normalize, store y (fp16 hi only) to g_yh [B*T][C] ----
    float inv0 = 1.f / l0r, inv1 = 1.f / l1r;
#pragma unroll
    for (int nt = 0; nt < 8; nt++) {
        int col = h * 64 + nt * 8 + (lane & 3) * 2;
        size_t row0 = (size_t)b * TT + r0g;
        size_t row1 = (size_t)b * TT + r1g;
        *(uint32_t*)(g_yh + row0 * CC + col) = pack2h(y[nt][0] * inv0, y[nt][1] * inv0);
        *(uint32_t*)(g_yh + row1 * CC + col) = pack2h(y[nt][2] * inv1, y[nt][3] * inv1);
    }
}

// ---------------------------------------------------------------------------
extern "C" void kernel_launch(void* const* d_in, const int* in_sizes, int n_in,
                              void* d_out, int out_size)
{
    const float* x    = (const float*)d_in[0];   // [B,T,C]
    const float* bias = (const float*)d_in[1];   // [1,H,T,T]
    const float* Wa   = (const float*)d_in[2];   // [3C,C]
    const float* Wp   = (const float*)d_in[3];   // [C,C]
    float* out = (float*)d_out;

    const int M = BB * TT;   // 4096

    void *xh, *xl, *wah, *wal, *wph, *wpl, *yh;
    cudaGetSymbolAddress(&xh, g_xh);   cudaGetSymbolAddress(&xl, g_xl);
    cudaGetSymbolAddress(&wah, g_wah); cudaGetSymbolAddress(&wal, g_wal);
    cudaGetSymbolAddress(&wph, g_wph); cudaGetSymbolAddress(&wpl, g_wpl);
    cudaGetSymbolAddress(&yh, g_yh);

    cudaFuncSetAttribute(gemm_h2<1>, cudaFuncAttributeMaxDynamicSharedMemorySize, GEMM_SMEM);
    cudaFuncSetAttribute(gemm_h2<0>, cudaFuncAttributeMaxDynamicSharedMemorySize, GEMM_SMEM);
    cudaFuncSetAttribute(attn_mma,   cudaFuncAttributeMaxDynamicSharedMemorySize, ATTN_SMEM);

    // 0) fused fp32 -> fp16 hi/lo split of x, W_attn, W_proj (float4 units)
    split_all<<<8192, 256>>>(x, Wa, Wp);

    // 1) QKV projection -> split q/k (3-pass) + v hi (1-pass) in [B,H,T,D]
    gemm_h2<1><<<dim3(3 * CC / 64, M / 128), 256, GEMM_SMEM>>>(
        (const __half*)xh, (const __half*)xl,
        (const __half*)wah, (const __half*)wal, nullptr, M, 3 * CC, CC);

    // 2) flash attention (HMMA, 64-row CTAs, 3/SM; batch-paired grid) -> y hi
    attn_mma<<<dim3(TT / 64 * BB, HH, 1), 128, ATTN_SMEM>>>(bias);

    // 3) output projection (2-pass: yh*Wh + yh*Wl) -> fp32 out
    gemm_h2<0><<<dim3(CC / 64, M / 128), 256, GEMM_SMEM>>>(
        (const __half*)yh, (const __half*)yh,
        (const __half*)wph, (const __half*)wpl, out, M, CC, CC);
}